// round 14
// baseline (speedup 1.0000x reference)
#include <cuda_runtime.h>

// Fixed problem shapes
#define T_STEPS 5
#define BS      32
#define C       64
#define H       64
#define W       64
#define VTH     1.0f
// gamma = DROP_RATE / BLOCK_SIZE^2 = 0.1 / 49
#define GAMMA   0.002040816326530612f

#define PLANE4      1024                      // H*W/4
#define VEC_PER_T   2097152                   // BS*C*H*W/4
#define MAX_SEEDS   256                       // E[k] ~ 4.6 per (b,h) region

// ---------------------------------------------------------------------------
// Single fused kernel, NO cross-block dependencies, zero prologue redundancy.
// Block = (b, h), 1024 threads = 64 channels x 16 float4 w-quads.
// Each thread owns ONE float4 site (R3's proven body shape: 1 u-state,
// 5 ld + 5 st).  Prologue (once per (b,h)):
//   gather seeds (mr < gamma) from mr[t][b][h-3..h+3][*], t=0..4 (560 float4,
//   one load per thread) -> keep(t,w) = !(seed same t with |pw-w| <= 3),
//   one smem entry per thread (320 total).
// ---------------------------------------------------------------------------
__global__ void __launch_bounds__(1024, 2)
fused_kernel(const float4* __restrict__ x,
             const float4* __restrict__ mr4,
             float4* __restrict__ out) {
    __shared__ int   s_cnt;
    __shared__ int   s_pts[MAX_SEEDS];                    // packed (t << 6) | w
    __shared__ __align__(16) float s_bm[T_STEPS * W];     // keep mask, all t

    const int bid = blockIdx.x;
    const int b   = bid >> 6;              // 0..31
    const int h   = bid & 63;              // 0..63
    const int tid = threadIdx.x;

    if (tid == 0) s_cnt = 0;
    __syncthreads();

    // ---- gather seeds: 560 float4 (5 t x 7 rows x 16 q), one per thread ----
    if (tid < T_STEPS * 7 * 16) {
        const int t  = tid / 112;
        const int rr = (tid - t * 112) >> 4;
        const int q  = tid & 15;
        const int r  = h - 3 + rr;
        if (r >= 0 && r < H) {
            const float4 v = mr4[((t * BS + b) << 10) + (r << 4) + q];
            const int w0 = q << 2;
            if (v.x < GAMMA) { int s = atomicAdd(&s_cnt, 1); if (s < MAX_SEEDS) s_pts[s] = (t << 6) | (w0 + 0); }
            if (v.y < GAMMA) { int s = atomicAdd(&s_cnt, 1); if (s < MAX_SEEDS) s_pts[s] = (t << 6) | (w0 + 1); }
            if (v.z < GAMMA) { int s = atomicAdd(&s_cnt, 1); if (s < MAX_SEEDS) s_pts[s] = (t << 6) | (w0 + 2); }
            if (v.w < GAMMA) { int s = atomicAdd(&s_cnt, 1); if (s < MAX_SEEDS) s_pts[s] = (t << 6) | (w0 + 3); }
        }
    }
    __syncthreads();

    // ---- build keep mask s_bm[t*64 + w]: one entry per thread (320) ----
    const int k = (s_cnt < MAX_SEEDS) ? s_cnt : MAX_SEEDS;
    if (tid < T_STEPS * W) {
        const int t = tid >> 6;
        const int w = tid & 63;
        float keep = 1.0f;
        for (int i = 0; i < k; ++i) {
            const int p = s_pts[i];
            if ((p >> 6) == t) {
                const int d = (p & 63) - w;
                if (d >= -3 && d <= 3) keep = 0.0f;
            }
        }
        s_bm[tid] = keep;
    }
    __syncthreads();

    // ---- LIF scan: one float4 site per thread (R3 body) ----
    const int q = tid & 15;
    const int c = tid >> 4;                               // 0..63
    const int base = ((((b << 6) | c) << 6) | h) * 16 + q;
    const float4* __restrict__ bm4s = reinterpret_cast<const float4*>(s_bm);

    float4 u = make_float4(0.f, 0.f, 0.f, 0.f);

    #pragma unroll
    for (int t = 0; t < T_STEPS; ++t) {
        const float4 xt = x[base + t * VEC_PER_T];
        const float4 bm = bm4s[(t << 4) + q];
        float4 o;

        u.x = (u.x > VTH) ? xt.x : fmaf(0.5f, u.x, xt.x);
        u.y = (u.y > VTH) ? xt.y : fmaf(0.5f, u.y, xt.y);
        u.z = (u.z > VTH) ? xt.z : fmaf(0.5f, u.z, xt.z);
        u.w = (u.w > VTH) ? xt.w : fmaf(0.5f, u.w, xt.w);

        o.x = (u.x > VTH) ? bm.x : 0.0f;
        o.y = (u.y > VTH) ? bm.y : 0.0f;
        o.z = (u.z > VTH) ? bm.z : 0.0f;
        o.w = (u.w > VTH) ? bm.w : 0.0f;

        out[base + t * VEC_PER_T] = o;
    }
}

extern "C" void kernel_launch(void* const* d_in, const int* in_sizes, int n_in,
                              void* d_out, int out_size) {
    const float4* x  = (const float4*)d_in[0];
    const float4* mr = (const float4*)d_in[1];
    float4* out      = (float4*)d_out;

    fused_kernel<<<BS * H, 1024>>>(x, mr, out);   // 2048 blocks
}

// round 15
// speedup vs baseline: 1.0765x; 1.0765x over previous
#include <cuda_runtime.h>

// Fixed problem shapes
#define T_STEPS 5
#define BS      32
#define C       64
#define H       64
#define W       64
#define VTH     1.0f
// gamma = DROP_RATE / BLOCK_SIZE^2 = 0.1 / 49
#define GAMMA   0.002040816326530612f

#define VEC_PER_T   2097152                   // BS*C*H*W/4

// ---------------------------------------------------------------------------
// Single fused kernel, NO cross-block dependencies (R13 shape, cheap prologue).
// Block = (b, h, cg): 16 channels x 64 w x 5 t; 256 threads, ONE float4
// site per thread (1 u-state, 5 ld + 5 st).
// Prologue: for each t, a 64-bit drop bitmap for output row h is built by
// atomicOr'ing dilated windows of the ~4.6 seeds found in mr[t][b][h-3..h+3].
// keep float mask then derived with a single shift per entry.
// ---------------------------------------------------------------------------
__global__ void __launch_bounds__(256)
fused_kernel(const float4* __restrict__ x,
             const float4* __restrict__ mr4,
             float4* __restrict__ out) {
    __shared__ unsigned long long s_drop[T_STEPS];
    __shared__ __align__(16) float s_bm[T_STEPS * W];     // keep mask, all t

    const int bid = blockIdx.x;
    const int b   = bid >> 8;              // 0..31
    const int h   = (bid >> 2) & 63;       // 0..63
    const int cg  = bid & 3;               // 0..3 (16 channels each)
    const int tid = threadIdx.x;

    if (tid < T_STEPS) s_drop[tid] = 0ull;
    __syncthreads();

    // ---- gather seeds: 560 float4 (5 t x 7 rows x 16 q), 3 fixed passes ----
    #pragma unroll
    for (int j = 0; j < 3; ++j) {
        const int i = tid + j * 256;
        if (i < T_STEPS * 7 * 16) {
            const int t  = i / 112;
            const int rr = (i - t * 112) >> 4;
            const int q  = i & 15;
            const int r  = h - 3 + rr;
            if (r >= 0 && r < H) {
                const float4 v = mr4[((t * BS + b) << 10) + (r << 4) + q];
                if (v.x < GAMMA || v.y < GAMMA || v.z < GAMMA || v.w < GAMMA) {
                    const int w0 = q << 2;
                    unsigned long long win = 0ull;
                    #define ADD_SEED(F, DW)                                   \
                        if (F < GAMMA) {                                      \
                            const int pw = w0 + DW;                           \
                            const int lo = (pw - 3 < 0) ? 0 : pw - 3;         \
                            const int hi = (pw + 3 > 63) ? 63 : pw + 3;       \
                            win |= (((1ull << (hi - lo + 1)) - 1ull) << lo);  \
                        }
                    ADD_SEED(v.x, 0) ADD_SEED(v.y, 1) ADD_SEED(v.z, 2) ADD_SEED(v.w, 3)
                    #undef ADD_SEED
                    atomicOr(&s_drop[t], win);
                }
            }
        }
    }
    __syncthreads();

    // ---- build keep mask s_bm[t*64 + w]: single shift per entry ----
    #pragma unroll
    for (int j = 0; j < 2; ++j) {
        const int idx = tid + j * 256;
        if (idx < T_STEPS * W) {
            const int t = idx >> 6;
            const int w = idx & 63;
            s_bm[idx] = ((s_drop[t] >> w) & 1ull) ? 0.0f : 1.0f;
        }
    }
    __syncthreads();

    // ---- LIF scan: one float4 site per thread (lean body) ----
    const int q = tid & 15;
    const int c = (cg << 4) + (tid >> 4);                 // 0..63
    const int base = ((((b << 6) | c) << 6) | h) * 16 + q;
    const float4* __restrict__ bm4s = reinterpret_cast<const float4*>(s_bm);

    float4 u = make_float4(0.f, 0.f, 0.f, 0.f);

    #pragma unroll
    for (int t = 0; t < T_STEPS; ++t) {
        const float4 xt = x[base + t * VEC_PER_T];
        const float4 bm = bm4s[(t << 4) + q];
        float4 o;

        u.x = (u.x > VTH) ? xt.x : fmaf(0.5f, u.x, xt.x);
        u.y = (u.y > VTH) ? xt.y : fmaf(0.5f, u.y, xt.y);
        u.z = (u.z > VTH) ? xt.z : fmaf(0.5f, u.z, xt.z);
        u.w = (u.w > VTH) ? xt.w : fmaf(0.5f, u.w, xt.w);

        o.x = (u.x > VTH) ? bm.x : 0.0f;
        o.y = (u.y > VTH) ? bm.y : 0.0f;
        o.z = (u.z > VTH) ? bm.z : 0.0f;
        o.w = (u.w > VTH) ? bm.w : 0.0f;

        out[base + t * VEC_PER_T] = o;
    }
}

extern "C" void kernel_launch(void* const* d_in, const int* in_sizes, int n_in,
                              void* d_out, int out_size) {
    const float4* x  = (const float4*)d_in[0];
    const float4* mr = (const float4*)d_in[1];
    float4* out      = (float4*)d_out;

    fused_kernel<<<BS * H * 4, 256>>>(x, mr, out);   // 8192 blocks
}

// round 16
// speedup vs baseline: 1.0808x; 1.0040x over previous
#include <cuda_runtime.h>

// Fixed problem shapes
#define T_STEPS 5
#define BS      32
#define C       64
#define H       64
#define W       64
#define VTH     1.0f
// gamma = DROP_RATE / BLOCK_SIZE^2 = 0.1 / 49
#define GAMMA   0.002040816326530612f

#define VEC_PER_T   2097152                   // BS*C*H*W/4

// ---------------------------------------------------------------------------
// Single fused kernel, NO cross-block dependencies.
// Block = (b, h, cg): cg in {0,1}, 32 channels x 64 w x 5 t; 512 threads,
// ONE float4 site per thread (1 u-state, 5 ld + 5 st).
// Prologue (bitmap formulation): for each t, a 64-bit drop bitmap for output
// row h is built by atomicOr'ing dilated windows of the ~4.6 seeds found in
// mr[t][b][h-3..h+3]; keep float mask derived with one shift per entry.
// ---------------------------------------------------------------------------
__global__ void __launch_bounds__(512)
fused_kernel(const float4* __restrict__ x,
             const float4* __restrict__ mr4,
             float4* __restrict__ out) {
    __shared__ unsigned long long s_drop[T_STEPS];
    __shared__ __align__(16) float s_bm[T_STEPS * W];     // keep mask, all t

    const int bid = blockIdx.x;
    const int b   = bid >> 7;              // 0..31
    const int h   = (bid >> 1) & 63;       // 0..63
    const int cg  = bid & 1;               // 0..1 (32 channels each)
    const int tid = threadIdx.x;

    if (tid < T_STEPS) s_drop[tid] = 0ull;
    __syncthreads();

    // ---- gather seeds: 560 float4 (5 t x 7 rows x 16 q), 2 fixed passes ----
    #pragma unroll
    for (int j = 0; j < 2; ++j) {
        const int i = tid + j * 512;
        if (i < T_STEPS * 7 * 16) {
            const int t  = i / 112;
            const int rr = (i - t * 112) >> 4;
            const int q  = i & 15;
            const int r  = h - 3 + rr;
            if (r >= 0 && r < H) {
                const float4 v = mr4[((t * BS + b) << 10) + (r << 4) + q];
                if (v.x < GAMMA || v.y < GAMMA || v.z < GAMMA || v.w < GAMMA) {
                    const int w0 = q << 2;
                    unsigned long long win = 0ull;
                    #define ADD_SEED(F, DW)                                   \
                        if (F < GAMMA) {                                      \
                            const int pw = w0 + DW;                           \
                            const int lo = (pw - 3 < 0) ? 0 : pw - 3;         \
                            const int hi = (pw + 3 > 63) ? 63 : pw + 3;       \
                            win |= (((1ull << (hi - lo + 1)) - 1ull) << lo);  \
                        }
                    ADD_SEED(v.x, 0) ADD_SEED(v.y, 1) ADD_SEED(v.z, 2) ADD_SEED(v.w, 3)
                    #undef ADD_SEED
                    atomicOr(&s_drop[t], win);
                }
            }
        }
    }
    __syncthreads();

    // ---- build keep mask s_bm[t*64 + w]: one shift per entry, single pass ----
    if (tid < T_STEPS * W) {
        const int t = tid >> 6;
        const int w = tid & 63;
        s_bm[tid] = ((s_drop[t] >> w) & 1ull) ? 0.0f : 1.0f;
    }
    __syncthreads();

    // ---- LIF scan: one float4 site per thread (lean body) ----
    const int q = tid & 15;
    const int c = (cg << 5) + (tid >> 4);                 // 0..63
    const int base = ((((b << 6) | c) << 6) | h) * 16 + q;
    const float4* __restrict__ bm4s = reinterpret_cast<const float4*>(s_bm);

    float4 u = make_float4(0.f, 0.f, 0.f, 0.f);

    #pragma unroll
    for (int t = 0; t < T_STEPS; ++t) {
        const float4 xt = x[base + t * VEC_PER_T];
        const float4 bm = bm4s[(t << 4) + q];
        float4 o;

        u.x = (u.x > VTH) ? xt.x : fmaf(0.5f, u.x, xt.x);
        u.y = (u.y > VTH) ? xt.y : fmaf(0.5f, u.y, xt.y);
        u.z = (u.z > VTH) ? xt.z : fmaf(0.5f, u.z, xt.z);
        u.w = (u.w > VTH) ? xt.w : fmaf(0.5f, u.w, xt.w);

        o.x = (u.x > VTH) ? bm.x : 0.0f;
        o.y = (u.y > VTH) ? bm.y : 0.0f;
        o.z = (u.z > VTH) ? bm.z : 0.0f;
        o.w = (u.w > VTH) ? bm.w : 0.0f;

        out[base + t * VEC_PER_T] = o;
    }
}

extern "C" void kernel_launch(void* const* d_in, const int* in_sizes, int n_in,
                              void* d_out, int out_size) {
    const float4* x  = (const float4*)d_in[0];
    const float4* mr = (const float4*)d_in[1];
    float4* out      = (float4*)d_out;

    fused_kernel<<<BS * H * 2, 512>>>(x, mr, out);   // 4096 blocks
}